// round 14
// baseline (speedup 1.0000x reference)
#include <cuda_runtime.h>
#include <cuda_fp16.h>

#define N_NODES  100000
#define N_EDGES  1600000
#define D        64
#define BUCK_SH  6            // bucket = dst >> 6  (64 nodes per bucket)
#define NBUCK    1563         // ceil(100000 / 64)
#define BUCK_CAP 2048         // slots per bucket (true count ~1024 +- 32)
#define EPB      4096         // edges per scatter block

#define WS_STRIDE 72          // bank = 8*t + g  -> conflict-free B-frag loads

// ---------------------------------------------------------------------------
// device scratch (zero-init at load; kernels restore invariants every launch)
// ---------------------------------------------------------------------------
__device__ __align__(16) __half2 g_supp_h[(size_t)N_NODES * 32];   // X@W fp16 (12.8 MB)
__device__ int  g_bcur[NBUCK];                                     // bucket cursors (K3 resets)
__device__ int2 g_ebuf[(size_t)NBUCK * BUCK_CAP];                  // bucketed edges (25.6 MB)

// ---------------------------------------------------------------------------
// Side stream + fork/join events (host objects only, created at module init).
// ---------------------------------------------------------------------------
static cudaStream_t g_s2 = nullptr;
static cudaEvent_t  g_evFork = nullptr, g_evJoin = nullptr;
struct HxStreamInit {
    HxStreamInit() {
        if (cudaStreamCreateWithFlags(&g_s2, cudaStreamNonBlocking) != cudaSuccess)
            g_s2 = nullptr;
        if (cudaEventCreateWithFlags(&g_evFork, cudaEventDisableTiming) != cudaSuccess)
            g_evFork = nullptr;
        if (cudaEventCreateWithFlags(&g_evJoin, cudaEventDisableTiming) != cudaSuccess)
            g_evJoin = nullptr;
    }
};
static HxStreamInit g_hx_stream_init;

__device__ __forceinline__ unsigned f2tf32(float f) {
    unsigned u;
    asm("cvt.rna.tf32.f32 %0, %1;" : "=r"(u) : "f"(f));
    return u;
}

// ---------------------------------------------------------------------------
// K1: GEMM  g_supp_h = fp16(X @ W)  via mma.sync.m16n8k8.tf32  (proven body)
// ---------------------------------------------------------------------------
__global__ void __launch_bounds__(256) gemm_kernel(const float* __restrict__ x,
                                                   const float* __restrict__ w) {
    __shared__ unsigned Ws[64 * WS_STRIDE];    // tf32-rounded W (18 KB)

    const int tid  = threadIdx.x;
    const int base = blockIdx.x * 128;

    {
        const float4* w4 = (const float4*)w;
#pragma unroll
        for (int j = 0; j < 4; j++) {
            int idx = tid + j * 256;
            float4 v = w4[idx];
            uint4 t;
            t.x = f2tf32(v.x); t.y = f2tf32(v.y); t.z = f2tf32(v.z); t.w = f2tf32(v.w);
            *(uint4*)&Ws[(idx >> 4) * WS_STRIDE + (idx & 15) * 4] = t;
        }
    }
    __syncthreads();

    const int wp   = tid >> 5;
    const int lane = tid & 31;
    const int g    = lane >> 2;
    const int t    = lane & 3;

    const int r0 = base + wp * 16 + g;
    const int r1 = r0 + 8;
    const bool ok0 = (r0 < N_NODES);
    const bool ok1 = (r1 < N_NODES);
    const float* xr0 = x + (size_t)r0 * 64 + t;
    const float* xr1 = x + (size_t)r1 * 64 + t;

    float af[8][4];
#pragma unroll
    for (int kk = 0; kk < 8; kk++) {
        af[kk][0] = ok0 ? __ldg(xr0 + kk * 8)     : 0.f;
        af[kk][1] = ok1 ? __ldg(xr1 + kk * 8)     : 0.f;
        af[kk][2] = ok0 ? __ldg(xr0 + kk * 8 + 4) : 0.f;
        af[kk][3] = ok1 ? __ldg(xr1 + kk * 8 + 4) : 0.f;
    }

    float c[8][4];
#pragma unroll
    for (int j = 0; j < 8; j++)
#pragma unroll
        for (int q = 0; q < 4; q++) c[j][q] = 0.f;

    const unsigned* ws0 = &Ws[t * WS_STRIDE + g];

#pragma unroll
    for (int kk = 0; kk < 8; kk++) {
        unsigned a0 = f2tf32(af[kk][0]);
        unsigned a1 = f2tf32(af[kk][1]);
        unsigned a2 = f2tf32(af[kk][2]);
        unsigned a3 = f2tf32(af[kk][3]);
        const unsigned* wk = ws0 + kk * 8 * WS_STRIDE;
#pragma unroll
        for (int j = 0; j < 8; j++) {
            unsigned b0 = wk[j * 8];
            unsigned b1 = wk[j * 8 + 4 * WS_STRIDE];
            asm volatile(
                "mma.sync.aligned.m16n8k8.row.col.f32.tf32.tf32.f32 "
                "{%0,%1,%2,%3}, {%4,%5,%6,%7}, {%8,%9}, {%0,%1,%2,%3};"
                : "+f"(c[j][0]), "+f"(c[j][1]), "+f"(c[j][2]), "+f"(c[j][3])
                : "r"(a0), "r"(a1), "r"(a2), "r"(a3), "r"(b0), "r"(b1));
        }
    }

#pragma unroll
    for (int j = 0; j < 8; j++) {
        int h2 = j * 4 + t;
        if (ok0)
            g_supp_h[(size_t)r0 * 32 + h2] = __floats2half2_rn(c[j][0], c[j][1]);
        if (ok1)
            g_supp_h[(size_t)r1 * 32 + h2] = __floats2half2_rn(c[j][2], c[j][3]);
    }
}

// ---------------------------------------------------------------------------
// K2: bucket scatter (unchanged, 64-node buckets)
// ---------------------------------------------------------------------------
__global__ void __launch_bounds__(256) bucket_scatter_kernel(const int* __restrict__ src,
                                                             const int* __restrict__ dst,
                                                             const float* __restrict__ adj) {
    __shared__ int bh[NBUCK];
    __shared__ int bbase[NBUCK];

    const int tid = threadIdx.x;
    const size_t q0 = (size_t)blockIdx.x * (EPB / 4);

    for (int i = tid; i < NBUCK; i += 256) bh[i] = 0;
    __syncthreads();

    int4 dv[4];
    bool ok[4];
#pragma unroll
    for (int j = 0; j < 4; j++) {
        size_t q = q0 + tid + j * 256;
        ok[j] = (q < N_EDGES / 4);
        if (ok[j]) {
            dv[j] = ((const int4*)dst)[q];
            atomicAdd(&bh[dv[j].x >> BUCK_SH], 1);
            atomicAdd(&bh[dv[j].y >> BUCK_SH], 1);
            atomicAdd(&bh[dv[j].z >> BUCK_SH], 1);
            atomicAdd(&bh[dv[j].w >> BUCK_SH], 1);
        }
    }
    __syncthreads();

    for (int i = tid; i < NBUCK; i += 256) {
        int cth = bh[i];
        if (cth > 0) bbase[i] = atomicAdd(&g_bcur[i], cth);
    }
    __syncthreads();

#pragma unroll
    for (int j = 0; j < 4; j++) {
        if (!ok[j]) continue;
        size_t q = q0 + tid + j * 256;
        int4   sv = ((const int4*)src)[q];
        float4 av = ((const float4*)adj)[q];
        int d4[4] = {dv[j].x, dv[j].y, dv[j].z, dv[j].w};
        int s4[4] = {sv.x, sv.y, sv.z, sv.w};
        float a4[4] = {av.x, av.y, av.z, av.w};
#pragma unroll
        for (int k = 0; k < 4; k++) {
            int b = d4[k] >> BUCK_SH;
            int r = atomicAdd(&bh[b], -1) - 1;
            int slot = bbase[b] + r;
            if (slot < BUCK_CAP)
                g_ebuf[(size_t)b * BUCK_CAP + slot] =
                    make_int2(s4[k] | ((d4[k] & 63) << 20), __float_as_int(a4[k]));
        }
    }
}

// ---------------------------------------------------------------------------
// K3: bucket gather with ATOMIC-FREE count-sort via __match_any_sync.
// Per-warp histograms + per-warp placement bases; leaders do plain smem RMW.
// ---------------------------------------------------------------------------
__global__ void __launch_bounds__(256) bucket_gather_kernel(const float* __restrict__ bias,
                                                            float* __restrict__ out) {
    __shared__ int2 list[BUCK_CAP];   // 16 KB sorted edge list
    __shared__ int  wcnt[8][64];      // per-warp node counts -> placement cursors
    __shared__ int  loffs[65];
    __shared__ int  wtot2[2];

    const int b    = blockIdx.x;
    const int tid  = threadIdx.x;
    const int lane = tid & 31;
    const int w    = tid >> 5;
    const unsigned lmask_lt = (1u << lane) - 1u;

    int cnt = g_bcur[b];
    if (cnt > BUCK_CAP) cnt = BUCK_CAP;

    // zero per-warp counters (512 ints)
    ((int*)wcnt)[tid]       = 0;
    ((int*)wcnt)[tid + 256] = 0;
    __syncthreads();

    // P1: load edges to registers + per-warp histogram via match_any (no atomics)
    int2 ev[8];
    int  nid[8];
    const int2* ebase = g_ebuf + (size_t)b * BUCK_CAP;
#pragma unroll
    for (int k = 0; k < 8; k++) {
        int i = tid + k * 256;
        bool valid = (i < cnt);
        ev[k]  = valid ? __ldg(&ebase[i]) : make_int2(0, 0);
        nid[k] = valid ? ((ev[k].x >> 20) & 63) : 127;     // 127 = sentinel
        unsigned mask = __match_any_sync(0xffffffffu, nid[k]);
        int leader = __ffs(mask) - 1;
        if (valid && lane == leader)
            wcnt[w][nid[k]] += __popc(mask);               // warp-exclusive RMW
    }
    __syncthreads();

    // P1b: totals per node -> exclusive scan -> per-warp placement bases
    int cts[8];
    int tot = 0, s = 0;
    if (tid < 64) {
#pragma unroll
        for (int wi = 0; wi < 8; wi++) { cts[wi] = wcnt[wi][tid]; tot += cts[wi]; }
        s = tot;
#pragma unroll
        for (int d = 1; d < 32; d <<= 1) {
            int t = __shfl_up_sync(0xffffffffu, s, d);
            if (lane >= d) s += t;
        }
        if (lane == 31) wtot2[tid >> 5] = s;
    }
    __syncthreads();
    if (tid == 0) { int t0 = wtot2[0]; wtot2[0] = 0; wtot2[1] = t0; }
    __syncthreads();
    if (tid < 64) {
        int off = (s - tot) + wtot2[tid >> 5];
        loffs[tid] = off;
        if (tid == 63) loffs[64] = off + tot;
        int run = off;
#pragma unroll
        for (int wi = 0; wi < 8; wi++) { wcnt[wi][tid] = run; run += cts[wi]; }
    }
    __syncthreads();

    // P2: placement via match_any ranks (no atomics)
#pragma unroll
    for (int k = 0; k < 8; k++) {
        int i = tid + k * 256;
        bool valid = (i < cnt);
        int  n = nid[k];
        unsigned mask = __match_any_sync(0xffffffffu, n);
        int leader = __ffs(mask) - 1;
        int rank = __popc(mask & lmask_lt);
        int basev = 0;
        if (valid && lane == leader) {
            basev = wcnt[w][n];
            wcnt[w][n] = basev + __popc(mask);
        }
        basev = __shfl_sync(0xffffffffu, basev, leader);
        if (valid)
            list[basev + rank] = make_int2(ev[k].x & 0xFFFFF, ev[k].y);
    }
    __syncthreads();

    // P3: gather — 8 lanes per node, 2 node-iterations (proven body)
    const int l = tid & 7;
    float4 b0 = ((const float4*)bias)[l * 2];
    float4 b1 = ((const float4*)bias)[l * 2 + 1];

    for (int it = 0; it < 2; it++) {
        int nl = (tid >> 3) + it * 32;
        int ng = b * 64 + nl;
        if (ng >= N_NODES) break;

        int e0 = loffs[nl];
        int e1 = loffs[nl + 1];

        float2 a0 = make_float2(0.f, 0.f), a1 = a0, a2 = a0, a3 = a0;

        int e = e0;
        for (; e + 4 <= e1; e += 4) {
#pragma unroll
            for (int u = 0; u < 4; u++) {
                int2 evu = list[e + u];
                float vv = __int_as_float(evu.y);
                union { uint4 uu; __half2 h[4]; } r;
                r.uu = *(const uint4*)(g_supp_h + ((size_t)evu.x << 5) + (l << 2));
                float2 f0 = __half22float2(r.h[0]), f1 = __half22float2(r.h[1]);
                float2 f2 = __half22float2(r.h[2]), f3 = __half22float2(r.h[3]);
                a0.x += vv * f0.x;  a0.y += vv * f0.y;
                a1.x += vv * f1.x;  a1.y += vv * f1.y;
                a2.x += vv * f2.x;  a2.y += vv * f2.y;
                a3.x += vv * f3.x;  a3.y += vv * f3.y;
            }
        }
        for (; e < e1; e++) {
            int2 evu = list[e];
            float vv = __int_as_float(evu.y);
            union { uint4 uu; __half2 h[4]; } r;
            r.uu = *(const uint4*)(g_supp_h + ((size_t)evu.x << 5) + (l << 2));
            float2 f0 = __half22float2(r.h[0]), f1 = __half22float2(r.h[1]);
            float2 f2 = __half22float2(r.h[2]), f3 = __half22float2(r.h[3]);
            a0.x += vv * f0.x;  a0.y += vv * f0.y;
            a1.x += vv * f1.x;  a1.y += vv * f1.y;
            a2.x += vv * f2.x;  a2.y += vv * f2.y;
            a3.x += vv * f3.x;  a3.y += vv * f3.y;
        }

        float* op = out + (size_t)ng * 64 + l * 8;
        *(float4*)op       = make_float4(a0.x + b0.x, a0.y + b0.y, a1.x + b0.z, a1.y + b0.w);
        *(float4*)(op + 4) = make_float4(a2.x + b1.x, a2.y + b1.y, a3.x + b1.z, a3.y + b1.w);
    }

    if (tid == 0) g_bcur[b] = 0;    // invariant for next launch
}

// ---------------------------------------------------------------------------
extern "C" void kernel_launch(void* const* d_in, const int* in_sizes, int n_in,
                              void* d_out, int out_size) {
    const float* x    = (const float*)d_in[0];
    const float* w    = (const float*)d_in[1];
    const float* bias = (const float*)d_in[2];
    const float* adj  = (const float*)d_in[3];
    const int*   src  = (const int*)d_in[4];
    const int*   dst  = (const int*)d_in[5];
    float*       out  = (float*)d_out;

    (void)in_sizes; (void)n_in; (void)out_size;

    const int sblk = (N_EDGES + EPB - 1) / EPB;         // 391
    const int gblk = (N_NODES + 127) / 128;             // 782

    const bool forked = (g_s2 != nullptr) && (g_evFork != nullptr) && (g_evJoin != nullptr);

    if (forked) {
        cudaEventRecord(g_evFork, 0);
        cudaStreamWaitEvent(g_s2, g_evFork, 0);
        gemm_kernel<<<gblk, 256, 0, g_s2>>>(x, w);
    } else {
        gemm_kernel<<<gblk, 256>>>(x, w);
    }

    bucket_scatter_kernel<<<sblk, 256>>>(src, dst, adj);

    if (forked) {
        cudaEventRecord(g_evJoin, g_s2);
        cudaStreamWaitEvent(0, g_evJoin, 0);
    }

    bucket_gather_kernel<<<NBUCK, 256>>>(bias, out);
}

// round 15
// speedup vs baseline: 1.1706x; 1.1706x over previous
#include <cuda_runtime.h>
#include <cuda_fp16.h>

#define N_NODES  100000
#define N_EDGES  1600000
#define D        64
#define BUCK_SH  6            // bucket = dst >> 6  (64 nodes per bucket)
#define NBUCK    1563         // ceil(100000 / 64)
#define BUCK_CAP 2048         // slots per bucket (true count ~1024 +- 32)
#define EPB      4096         // edges per scatter block

#define WS_STRIDE 72          // bank = 8*t + g  -> conflict-free B-frag loads

// ---------------------------------------------------------------------------
// device scratch (zero-init at load; kernels restore invariants every launch)
// ---------------------------------------------------------------------------
__device__ __align__(16) __half2 g_supp_h[(size_t)N_NODES * 32];   // X@W fp16 (12.8 MB)
__device__ int  g_bcur[NBUCK];                                     // bucket cursors (K3 resets)
__device__ int2 g_ebuf[(size_t)NBUCK * BUCK_CAP];                  // bucketed edges (25.6 MB)

// ---------------------------------------------------------------------------
// Side stream + fork/join events (host objects only, created at module init).
// ---------------------------------------------------------------------------
static cudaStream_t g_s2 = nullptr;
static cudaEvent_t  g_evFork = nullptr, g_evJoin = nullptr;
struct HxStreamInit {
    HxStreamInit() {
        if (cudaStreamCreateWithFlags(&g_s2, cudaStreamNonBlocking) != cudaSuccess)
            g_s2 = nullptr;
        if (cudaEventCreateWithFlags(&g_evFork, cudaEventDisableTiming) != cudaSuccess)
            g_evFork = nullptr;
        if (cudaEventCreateWithFlags(&g_evJoin, cudaEventDisableTiming) != cudaSuccess)
            g_evJoin = nullptr;
    }
};
static HxStreamInit g_hx_stream_init;

__device__ __forceinline__ unsigned f2tf32(float f) {
    unsigned u;
    asm("cvt.rna.tf32.f32 %0, %1;" : "=r"(u) : "f"(f));
    return u;
}

// ---------------------------------------------------------------------------
// K1: GEMM  g_supp_h = fp16(X @ W)  via mma.sync.m16n8k8.tf32  (proven body)
// ---------------------------------------------------------------------------
__global__ void __launch_bounds__(256) gemm_kernel(const float* __restrict__ x,
                                                   const float* __restrict__ w) {
    __shared__ unsigned Ws[64 * WS_STRIDE];    // tf32-rounded W (18 KB)

    const int tid  = threadIdx.x;
    const int base = blockIdx.x * 128;

    {
        const float4* w4 = (const float4*)w;
#pragma unroll
        for (int j = 0; j < 4; j++) {
            int idx = tid + j * 256;
            float4 v = w4[idx];
            uint4 t;
            t.x = f2tf32(v.x); t.y = f2tf32(v.y); t.z = f2tf32(v.z); t.w = f2tf32(v.w);
            *(uint4*)&Ws[(idx >> 4) * WS_STRIDE + (idx & 15) * 4] = t;
        }
    }
    __syncthreads();

    const int wp   = tid >> 5;
    const int lane = tid & 31;
    const int g    = lane >> 2;
    const int t    = lane & 3;

    const int r0 = base + wp * 16 + g;
    const int r1 = r0 + 8;
    const bool ok0 = (r0 < N_NODES);
    const bool ok1 = (r1 < N_NODES);
    const float* xr0 = x + (size_t)r0 * 64 + t;
    const float* xr1 = x + (size_t)r1 * 64 + t;

    float af[8][4];
#pragma unroll
    for (int kk = 0; kk < 8; kk++) {
        af[kk][0] = ok0 ? __ldg(xr0 + kk * 8)     : 0.f;
        af[kk][1] = ok1 ? __ldg(xr1 + kk * 8)     : 0.f;
        af[kk][2] = ok0 ? __ldg(xr0 + kk * 8 + 4) : 0.f;
        af[kk][3] = ok1 ? __ldg(xr1 + kk * 8 + 4) : 0.f;
    }

    float c[8][4];
#pragma unroll
    for (int j = 0; j < 8; j++)
#pragma unroll
        for (int q = 0; q < 4; q++) c[j][q] = 0.f;

    const unsigned* ws0 = &Ws[t * WS_STRIDE + g];

#pragma unroll
    for (int kk = 0; kk < 8; kk++) {
        unsigned a0 = f2tf32(af[kk][0]);
        unsigned a1 = f2tf32(af[kk][1]);
        unsigned a2 = f2tf32(af[kk][2]);
        unsigned a3 = f2tf32(af[kk][3]);
        const unsigned* wk = ws0 + kk * 8 * WS_STRIDE;
#pragma unroll
        for (int j = 0; j < 8; j++) {
            unsigned b0 = wk[j * 8];
            unsigned b1 = wk[j * 8 + 4 * WS_STRIDE];
            asm volatile(
                "mma.sync.aligned.m16n8k8.row.col.f32.tf32.tf32.f32 "
                "{%0,%1,%2,%3}, {%4,%5,%6,%7}, {%8,%9}, {%0,%1,%2,%3};"
                : "+f"(c[j][0]), "+f"(c[j][1]), "+f"(c[j][2]), "+f"(c[j][3])
                : "r"(a0), "r"(a1), "r"(a2), "r"(a3), "r"(b0), "r"(b1));
        }
    }

#pragma unroll
    for (int j = 0; j < 8; j++) {
        int h2 = j * 4 + t;
        if (ok0)
            g_supp_h[(size_t)r0 * 32 + h2] = __floats2half2_rn(c[j][0], c[j][1]);
        if (ok1)
            g_supp_h[(size_t)r1 * 32 + h2] = __floats2half2_rn(c[j][2], c[j][3]);
    }
}

// ---------------------------------------------------------------------------
// K2: bucket scatter (unchanged R12 body, 64-node buckets)
// ---------------------------------------------------------------------------
__global__ void __launch_bounds__(256) bucket_scatter_kernel(const int* __restrict__ src,
                                                             const int* __restrict__ dst,
                                                             const float* __restrict__ adj) {
    __shared__ int bh[NBUCK];
    __shared__ int bbase[NBUCK];

    const int tid = threadIdx.x;
    const size_t q0 = (size_t)blockIdx.x * (EPB / 4);

    for (int i = tid; i < NBUCK; i += 256) bh[i] = 0;
    __syncthreads();

    int4 dv[4];
    bool ok[4];
#pragma unroll
    for (int j = 0; j < 4; j++) {
        size_t q = q0 + tid + j * 256;
        ok[j] = (q < N_EDGES / 4);
        if (ok[j]) {
            dv[j] = ((const int4*)dst)[q];
            atomicAdd(&bh[dv[j].x >> BUCK_SH], 1);
            atomicAdd(&bh[dv[j].y >> BUCK_SH], 1);
            atomicAdd(&bh[dv[j].z >> BUCK_SH], 1);
            atomicAdd(&bh[dv[j].w >> BUCK_SH], 1);
        }
    }
    __syncthreads();

    for (int i = tid; i < NBUCK; i += 256) {
        int cth = bh[i];
        if (cth > 0) bbase[i] = atomicAdd(&g_bcur[i], cth);
    }
    __syncthreads();

#pragma unroll
    for (int j = 0; j < 4; j++) {
        if (!ok[j]) continue;
        size_t q = q0 + tid + j * 256;
        int4   sv = ((const int4*)src)[q];
        float4 av = ((const float4*)adj)[q];
        int d4[4] = {dv[j].x, dv[j].y, dv[j].z, dv[j].w};
        int s4[4] = {sv.x, sv.y, sv.z, sv.w};
        float a4[4] = {av.x, av.y, av.z, av.w};
#pragma unroll
        for (int k = 0; k < 4; k++) {
            int b = d4[k] >> BUCK_SH;
            int r = atomicAdd(&bh[b], -1) - 1;
            int slot = bbase[b] + r;
            if (slot < BUCK_CAP)
                g_ebuf[(size_t)b * BUCK_CAP + slot] =
                    make_int2(s4[k] | ((d4[k] & 63) << 20), __float_as_int(a4[k]));
        }
    }
}

// ---------------------------------------------------------------------------
// K3: bucket gather. R12 atomic count-sort (proven) with int4 edge loads in
// P1, and a software-pipelined P3 (next batch's LDS+LDG issued before current
// batch's FMAs -> one exposed L2 round per node instead of four).
// ---------------------------------------------------------------------------
__global__ void __launch_bounds__(256) bucket_gather_kernel(const float* __restrict__ bias,
                                                            float* __restrict__ out) {
    __shared__ int2 list[BUCK_CAP];   // 16 KB sorted edge list
    __shared__ int  lcnt[64];
    __shared__ int  loffs[65];
    __shared__ int  lcur[64];
    __shared__ int  wtot[2];

    const int b    = blockIdx.x;
    const int tid  = threadIdx.x;
    const int lane = tid & 31;

    int cnt = g_bcur[b];
    if (cnt > BUCK_CAP) cnt = BUCK_CAP;

    if (tid < 64) lcnt[tid] = 0;
    __syncthreads();

    // P1: int4 loads (2 edges each) + smem histogram
    int4 ev4[4];
    bool ok0[4], ok1[4];
    const int4* ebase4 = (const int4*)(g_ebuf + (size_t)b * BUCK_CAP);
#pragma unroll
    for (int k = 0; k < 4; k++) {
        int q = tid + k * 256;
        ok0[k] = (2 * q     < cnt);
        ok1[k] = (2 * q + 1 < cnt);
        if (ok0[k]) {
            ev4[k] = __ldg(&ebase4[q]);
            atomicAdd(&lcnt[(ev4[k].x >> 20) & 63], 1);
            if (ok1[k]) atomicAdd(&lcnt[(ev4[k].z >> 20) & 63], 1);
        }
    }
    __syncthreads();

    // scan 64 counters -> exclusive loffs (2 warps + fixup)
    int v = 0, s = 0;
    if (tid < 64) {
        v = lcnt[tid];
        s = v;
#pragma unroll
        for (int d = 1; d < 32; d <<= 1) {
            int t = __shfl_up_sync(0xffffffffu, s, d);
            if (lane >= d) s += t;
        }
        if (lane == 31) wtot[tid >> 5] = s;
    }
    __syncthreads();
    if (tid == 0) {
        int t0 = wtot[0], t1 = wtot[1];
        wtot[0] = 0; wtot[1] = t0;
        loffs[64] = t0 + t1;
    }
    __syncthreads();
    if (tid < 64) {
        int o = (s - v) + wtot[tid >> 5];
        loffs[tid] = o;
        lcur[tid]  = o;
    }
    __syncthreads();

    // P2: place into sorted smem list (returning smem atomics, proven cheap)
#pragma unroll
    for (int k = 0; k < 4; k++) {
        if (ok0[k]) {
            int dl = (ev4[k].x >> 20) & 63;
            int r  = atomicAdd(&lcur[dl], 1);
            list[r] = make_int2(ev4[k].x & 0xFFFFF, ev4[k].y);
            if (ok1[k]) {
                int dl2 = (ev4[k].z >> 20) & 63;
                int r2  = atomicAdd(&lcur[dl2], 1);
                list[r2] = make_int2(ev4[k].z & 0xFFFFF, ev4[k].w);
            }
        }
    }
    __syncthreads();

    // P3: gather, software-pipelined — 8 lanes per node, 2 node-iterations
    const int l = tid & 7;
    float4 b0 = ((const float4*)bias)[l * 2];
    float4 b1 = ((const float4*)bias)[l * 2 + 1];

    for (int it = 0; it < 2; it++) {
        int nl = (tid >> 3) + it * 32;
        int ng = b * 64 + nl;
        if (ng >= N_NODES) break;

        int e0  = loffs[nl];
        int deg = loffs[nl + 1] - e0;

        float2 a0 = make_float2(0.f, 0.f), a1 = a0, a2 = a0, a3 = a0;

        if (deg > 0) {
            int2  cur[4];
            uint4 rcur[4];
            bool  vc[4];
            // prologue: batch 0 edges + rows
#pragma unroll
            for (int u = 0; u < 4; u++) {
                vc[u]  = (u < deg);
                cur[u] = list[vc[u] ? e0 + u : e0];
            }
#pragma unroll
            for (int u = 0; u < 4; u++)
                if (vc[u])
                    rcur[u] = *(const uint4*)(g_supp_h + ((size_t)cur[u].x << 5) + (l << 2));

            for (int c = 4;; c += 4) {
                bool more = (c < deg);
                int2  nxt[4];
                uint4 rnxt[4];
                bool  vn[4];
                if (more) {
                    // issue next batch's LDS + LDG BEFORE consuming current rows
#pragma unroll
                    for (int u = 0; u < 4; u++) {
                        vn[u]  = (c + u < deg);
                        nxt[u] = list[vn[u] ? e0 + c + u : e0];
                    }
#pragma unroll
                    for (int u = 0; u < 4; u++)
                        if (vn[u])
                            rnxt[u] = *(const uint4*)(g_supp_h + ((size_t)nxt[u].x << 5) + (l << 2));
                }
                // consume current batch
#pragma unroll
                for (int u = 0; u < 4; u++) {
                    if (vc[u]) {
                        float vv = __int_as_float(cur[u].y);
                        union { uint4 uu; __half2 h[4]; } r;
                        r.uu = rcur[u];
                        float2 f0 = __half22float2(r.h[0]), f1 = __half22float2(r.h[1]);
                        float2 f2 = __half22float2(r.h[2]), f3 = __half22float2(r.h[3]);
                        a0.x += vv * f0.x;  a0.y += vv * f0.y;
                        a1.x += vv * f1.x;  a1.y += vv * f1.y;
                        a2.x += vv * f2.x;  a2.y += vv * f2.y;
                        a3.x += vv * f3.x;  a3.y += vv * f3.y;
                    }
                }
                if (!more) break;
#pragma unroll
                for (int u = 0; u < 4; u++) {
                    cur[u] = nxt[u]; rcur[u] = rnxt[u]; vc[u] = vn[u];
                }
            }
        }

        float* op = out + (size_t)ng * 64 + l * 8;
        *(float4*)op       = make_float4(a0.x + b0.x, a0.y + b0.y, a1.x + b0.z, a1.y + b0.w);
        *(float4*)(op + 4) = make_float4(a2.x + b1.x, a2.y + b1.y, a3.x + b1.z, a3.y + b1.w);
    }

    if (tid == 0) g_bcur[b] = 0;    // invariant for next launch
}

// ---------------------------------------------------------------------------
extern "C" void kernel_launch(void* const* d_in, const int* in_sizes, int n_in,
                              void* d_out, int out_size) {
    const float* x    = (const float*)d_in[0];
    const float* w    = (const float*)d_in[1];
    const float* bias = (const float*)d_in[2];
    const float* adj  = (const float*)d_in[3];
    const int*   src  = (const int*)d_in[4];
    const int*   dst  = (const int*)d_in[5];
    float*       out  = (float*)d_out;

    (void)in_sizes; (void)n_in; (void)out_size;

    const int sblk = (N_EDGES + EPB - 1) / EPB;         // 391
    const int gblk = (N_NODES + 127) / 128;             // 782

    const bool forked = (g_s2 != nullptr) && (g_evFork != nullptr) && (g_evJoin != nullptr);

    if (forked) {
        cudaEventRecord(g_evFork, 0);
        cudaStreamWaitEvent(g_s2, g_evFork, 0);
        gemm_kernel<<<gblk, 256, 0, g_s2>>>(x, w);
    } else {
        gemm_kernel<<<gblk, 256>>>(x, w);
    }

    bucket_scatter_kernel<<<sblk, 256>>>(src, dst, adj);

    if (forked) {
        cudaEventRecord(g_evJoin, g_s2);
        cudaStreamWaitEvent(0, g_evJoin, 0);
    }

    bucket_gather_kernel<<<NBUCK, 256>>>(bias, out);
}